// round 6
// baseline (speedup 1.0000x reference)
#include <cuda_runtime.h>
#include <stdint.h>

#define NCONCEPTS 4096
#define CDIM      1024
#define BATCH     4096
#define KSAMP     256

// Scratch (allocation-free rule: device globals).
__device__ float    g_s[NCONCEPTS];                    // 16 KB
__device__ unsigned g_mask[BATCH * (NCONCEPTS / 32)];  // 2 MB bitmask, 128 words/row

// ---------------------------------------------------------------------------
// Kernel 1 (prep): mask build for 8 batch rows + row-dots for 8 concept rows.
// Row-dot loads are front-batched into registers to maximize MLP.
// ---------------------------------------------------------------------------
__global__ __launch_bounds__(256) void prep_kernel(
    const float* __restrict__ cb, const float* __restrict__ attn,
    const int* __restrict__ sampled_idx)
{
    __shared__ unsigned bm[8 * 128];   // 8 rows x 128 words = 4 KB

    const int t    = threadIdx.x;
    const int warp = t >> 5;
    const int lane = t & 31;

    reinterpret_cast<uint4*>(bm)[t] = make_uint4(0u, 0u, 0u, 0u);
    __syncthreads();

    // 8 rows' indices = 2048 contiguous ints = 512 int4; 2 per thread.
    {
        const int4* i4 = reinterpret_cast<const int4*>(
            sampled_idx + (size_t)blockIdx.x * 8 * KSAMP);
        #pragma unroll
        for (int j = 0; j < 2; j++) {
            int p  = t + j * 256;
            int4 v = i4[p];
            int r  = p >> 6;
            int a  = v.x & (NCONCEPTS - 1);
            int b  = v.y & (NCONCEPTS - 1);
            int c  = v.z & (NCONCEPTS - 1);
            int d  = v.w & (NCONCEPTS - 1);
            atomicOr(&bm[r * 128 + (a >> 5)], 1u << (a & 31));
            atomicOr(&bm[r * 128 + (b >> 5)], 1u << (b & 31));
            atomicOr(&bm[r * 128 + (c >> 5)], 1u << (c & 31));
            atomicOr(&bm[r * 128 + (d >> 5)], 1u << (d & 31));
        }
    }

    // Row-dot, one warp per concept row, loads fully front-batched.
    {
        const int row = blockIdx.x * 8 + warp;
        const float4* c4 = reinterpret_cast<const float4*>(cb   + (size_t)row * CDIM);
        const float4* a4 = reinterpret_cast<const float4*>(attn + (size_t)row * CDIM);

        float4 c[8], a[8];
        #pragma unroll
        for (int i = 0; i < 8; i++) c[i] = c4[lane + i * 32];
        #pragma unroll
        for (int i = 0; i < 8; i++) a[i] = a4[lane + i * 32];

        float sum = 0.f;
        #pragma unroll
        for (int i = 0; i < 8; i++)
            sum += c[i].x * a[i].x + c[i].y * a[i].y
                 + c[i].z * a[i].z + c[i].w * a[i].w;

        #pragma unroll
        for (int o = 16; o > 0; o >>= 1)
            sum += __shfl_xor_sync(0xFFFFFFFFu, sum, o);
        if (lane == 0) g_s[row] = sum;
    }

    __syncthreads();
    reinterpret_cast<uint4*>(g_mask + (size_t)blockIdx.x * 1024)[t] =
        reinterpret_cast<const uint4*>(bm)[t];
}

// ---------------------------------------------------------------------------
// Kernel 2 (store): pure streaming with 256-bit stores.
// CTA = (half-row stripe of 2048 floats) x (group of 8 rows). grid = 2x512.
// Thread owns 8 consecutive floats (col8) per row: warp stores 1KB contiguous
// per STG.256. Per thread: 2 s-loads, 8 mask loads (broadcast), 8 STG.256.
// ---------------------------------------------------------------------------
__global__ __launch_bounds__(256) void store_kernel(float* __restrict__ out)
{
#if (__CUDACC_VER_MAJOR__ >= 12)
    cudaGridDependencySynchronize();   // PDL: wait for prep results
#endif
    const int t      = threadIdx.x;
    const int stripe = blockIdx.x & 1;
    const int rg     = blockIdx.x >> 1;          // row group of 8
    const int col8   = stripe * 256 + t;         // unit of 8 floats; [0,512)/row

    const float4* s4 = reinterpret_cast<const float4*>(g_s);
    const float4 sa = s4[col8 * 2 + 0];
    const float4 sb = s4[col8 * 2 + 1];

    const int word = col8 >> 2;                  // 4 col8-units per mask word
    const int sh   = (col8 & 3) * 8;

    const unsigned* mp = g_mask + (size_t)rg * 8 * 128 + word;
    unsigned w[8];
    #pragma unroll
    for (int r = 0; r < 8; r++) w[r] = mp[r * 128];

    float* ob = out + (size_t)rg * 8 * NCONCEPTS + (size_t)col8 * 8;
    #pragma unroll
    for (int r = 0; r < 8; r++) {
        unsigned b = w[r] >> sh;
        float v0 = (b &   1u) ? sa.x : 0.f;
        float v1 = (b &   2u) ? sa.y : 0.f;
        float v2 = (b &   4u) ? sa.z : 0.f;
        float v3 = (b &   8u) ? sa.w : 0.f;
        float v4 = (b &  16u) ? sb.x : 0.f;
        float v5 = (b &  32u) ? sb.y : 0.f;
        float v6 = (b &  64u) ? sb.z : 0.f;
        float v7 = (b & 128u) ? sb.w : 0.f;
        asm volatile(
            "st.global.v8.f32 [%0], {%1,%2,%3,%4,%5,%6,%7,%8};"
            :: "l"(ob + (size_t)r * NCONCEPTS),
               "f"(v0), "f"(v1), "f"(v2), "f"(v3),
               "f"(v4), "f"(v5), "f"(v6), "f"(v7)
            : "memory");
    }
}

extern "C" void kernel_launch(void* const* d_in, const int* in_sizes, int n_in,
                              void* d_out, int out_size)
{
    const float* cb   = (const float*)d_in[0];
    const float* attn = (const float*)d_in[1];
    const int*   idx  = (const int*)d_in[2];
    float*       out  = (float*)d_out;

    prep_kernel<<<NCONCEPTS / 8, 256>>>(cb, attn, idx);

    // Store kernel with programmatic dependent launch to hide launch latency.
    cudaLaunchConfig_t cfg = {};
    cfg.gridDim  = dim3(1024, 1, 1);
    cfg.blockDim = dim3(256, 1, 1);
    cudaLaunchAttribute attrs[1];
    attrs[0].id = cudaLaunchAttributeProgrammaticStreamSerialization;
    attrs[0].val.programmaticStreamSerializationAllowed = 1;
    cfg.attrs = attrs;
    cfg.numAttrs = 1;
    cudaLaunchKernelEx(&cfg, store_kernel, out);
}